// round 1
// baseline (speedup 1.0000x reference)
#include <cuda_runtime.h>
#include <math.h>

#define BATCH 8
#define IMH 512
#define IMW 512
#define NP 11
#define FH 128
#define FW 128

// packed derived parameters
// [0,539)    sw   : 11 score filters, 7x7 each          (sw[k*49+tap])
// [539,550)  sbias: 11 score biases
// [550,844)  cw   : 3 cascades x 2 dims x 49 taps       (cw[(i*2+j)*49+tap])
// [844,850)  cb   : 3 cascades x 2 dims
#define OFF_SW    0
#define OFF_SBIAS 539
#define OFF_CW    550
#define OFF_CB    844
#define NPARAMS   850

__device__    float g_params_dev[NPARAMS];
__constant__  float c_params[NPARAMS];

__device__ float g_scores[BATCH * NP * FH * FW];
__device__ float g_pval[BATCH * NP * 4];
__device__ int   g_pidx[BATCH * NP * 4];

// ---------------------------------------------------------------------------
// Kernel 1: fold weights.
//   w_eff[c,tap] = sum_i backbone_w[c,i,tap]          (3 identical input chans)
//   sw[k,tap]    = sum_c fc_w[k,c] * w_eff[c,tap]
//   sbias[k]     = fc_b[k] + sum_c fc_w[k,c]*bb[c]
//   cw[i,j,tap]  = sum_c head_w[i,c,j] * w_eff[c,tap]
//   cb[i,j]      = head_b[i,j] + sum_c head_w[i,c,j]*bb[c]
// ---------------------------------------------------------------------------
__global__ void prep_kernel(const float* __restrict__ bw,
                            const float* __restrict__ bb,
                            const float* __restrict__ fcw,
                            const float* __restrict__ fcb,
                            const float* __restrict__ hw,
                            const float* __restrict__ hb) {
    int t = threadIdx.x;
    if (t < 539) {                       // sw
        int k = t / 49, p = t % 49;
        float acc = 0.f;
        #pragma unroll 4
        for (int c = 0; c < 256; ++c) {
            float we = bw[(c * 3 + 0) * 49 + p] + bw[(c * 3 + 1) * 49 + p] +
                       bw[(c * 3 + 2) * 49 + p];
            acc += fcw[k * 256 + c] * we;
        }
        g_params_dev[OFF_SW + t] = acc;
    } else if (t < 550) {                // sbias
        int k = t - 539;
        float acc = fcb[k];
        for (int c = 0; c < 256; ++c) acc += fcw[k * 256 + c] * bb[c];
        g_params_dev[OFF_SBIAS + k] = acc;
    } else if (t < 844) {                // cw
        int u = t - 550;
        int p = u % 49, ij = u / 49;     // ij = i*2 + j
        float acc = 0.f;
        #pragma unroll 4
        for (int c = 0; c < 256; ++c) {
            float we = bw[(c * 3 + 0) * 49 + p] + bw[(c * 3 + 1) * 49 + p] +
                       bw[(c * 3 + 2) * 49 + p];
            acc += hw[((ij >> 1) * 256 + c) * 2 + (ij & 1)] * we;
        }
        g_params_dev[OFF_CW + u] = acc;
    } else if (t < 850) {                // cb
        int u = t - 844;
        float acc = hb[u];
        for (int c = 0; c < 256; ++c)
            acc += hw[((u >> 1) * 256 + c) * 2 + (u & 1)] * bb[c];
        g_params_dev[OFF_CB + u] = acc;
    }
}

// ---------------------------------------------------------------------------
// Kernel 2: 11-channel 7x7 stride-4 pad-3 conv of normalized image -> scores.
// Block handles one batch x (16 x 32) output tile; input tile staged in smem.
// Score filter weights come from __constant__ -> FFMA immediate operands.
// ---------------------------------------------------------------------------
__global__ void conv_kernel(const float* __restrict__ img) {
    __shared__ float tile[70 * 134];
    const int tx = blockIdx.x;           // 0..3  (32-wide col tiles)
    const int ty = blockIdx.y;           // 0..7  (16-high row tiles)
    const int b  = blockIdx.z;
    const int tid = threadIdx.x;         // 256

    const float* imb = img + (size_t)b * IMH * IMW;
    const int ir0 = ty * 64 - 3;
    const int ic0 = tx * 128 - 3;

    for (int i = tid; i < 70 * 134; i += 256) {
        int r = i / 134, c = i - r * 134;
        int gr = ir0 + r, gc = ic0 + c;
        float v = 0.f;
        if (gr >= 0 && gr < IMH && gc >= 0 && gc < IMW)
            v = imb[gr * IMW + gc] - 0.5f;
        tile[i] = v;
    }
    __syncthreads();

    #pragma unroll
    for (int it = 0; it < 2; ++it) {
        int pos = tid + it * 256;        // 0..511
        int oyl = pos >> 5, oxl = pos & 31;
        float acc[NP];
        #pragma unroll
        for (int k = 0; k < NP; ++k) acc[k] = c_params[OFF_SBIAS + k];
        #pragma unroll
        for (int kh = 0; kh < 7; ++kh) {
            #pragma unroll
            for (int kw = 0; kw < 7; ++kw) {
                float v = tile[(oyl * 4 + kh) * 134 + oxl * 4 + kw];
                #pragma unroll
                for (int k = 0; k < NP; ++k)
                    acc[k] += v * c_params[OFF_SW + k * 49 + kh * 7 + kw];
            }
        }
        int oy = ty * 16 + oyl, ox = tx * 32 + oxl;
        #pragma unroll
        for (int k = 0; k < NP; ++k)
            g_scores[((b * NP + k) * FH + oy) * FW + ox] = acc[k];
    }
}

// ---------------------------------------------------------------------------
// Kernel 3: argmax over the bilinear-upsampled (align_corners) 512x512 field.
// sigmoid is monotone -> argmax(scores_up). Grid (4 splits, 88 maps),
// 512 threads: thread = output column, scans its 128 rows.
// Matches JAX: ys = oy * fl(127/511); top = a*(1-wy)+c*wy; v = t0*(1-wx)+t1*wx
// First-occurrence tie-break (row-major index).
// ---------------------------------------------------------------------------
__global__ void argmax_kernel() {
    const float STEP = 127.0f / 511.0f;
    const int split = blockIdx.x;
    const int m     = blockIdx.y;
    const int tid   = threadIdx.x;       // 512
    const int r0    = split * 128;

    int ylo = (int)(r0 * STEP);
    int yhi = (int)((r0 + 127) * STEP) + 1;
    if (yhi > 127) yhi = 127;
    int nrows = yhi - ylo + 1;           // <= 34

    __shared__ float s[34 * 128];
    const float* sm = g_scores + (size_t)m * FH * FW;
    for (int i = tid; i < nrows * 128; i += 512) s[i] = sm[ylo * 128 + i];
    __syncthreads();

    const int ox = tid;
    float xs = (float)ox * STEP;
    int x0 = (int)xs;
    int x1 = min(x0 + 1, 127);
    float wx = xs - (float)x0, omwx = 1.f - wx;

    float best = -1e30f;
    int boy = r0;
    for (int oy = r0; oy < r0 + 128; ++oy) {
        float ys = (float)oy * STEP;
        int y0 = (int)ys;
        float wy = ys - (float)y0, omwy = 1.f - wy;
        int y1 = min(y0 + 1, 127);
        const float* p0 = s + (y0 - ylo) * 128;
        const float* p1 = s + (y1 - ylo) * 128;
        float a = p0[x0], bq = p0[x1], c = p1[x0], d = p1[x1];
        float t0 = a * omwy + c * wy;
        float t1 = bq * omwy + d * wy;
        float v  = t0 * omwx + t1 * wx;
        if (v > best) { best = v; boy = oy; }
    }
    int bidx = boy * 512 + ox;

    __shared__ float rv[512];
    __shared__ int   ri[512];
    rv[tid] = best; ri[tid] = bidx;
    __syncthreads();
    for (int sft = 256; sft > 0; sft >>= 1) {
        if (tid < sft) {
            float v2 = rv[tid + sft]; int i2 = ri[tid + sft];
            if (v2 > rv[tid] || (v2 == rv[tid] && i2 < ri[tid])) {
                rv[tid] = v2; ri[tid] = i2;
            }
        }
        __syncthreads();
    }
    if (tid == 0) { g_pval[m * 4 + split] = rv[0]; g_pidx[m * 4 + split] = ri[0]; }
}

// ---------------------------------------------------------------------------
// Kernel 4: combine split partials -> coords, then 3 cascade refinements.
// Each cascade = gather 7x7 image patch at rounded coords, two 49-tap dots.
// Block = one (batch, point); 64 threads (49 active for the patch).
// ---------------------------------------------------------------------------
__global__ void cascade_kernel(const float* __restrict__ img,
                               float* __restrict__ out) {
    const int m = blockIdx.x;            // b*11 + p
    const int b = m / NP;
    const int tid = threadIdx.x;         // 64

    __shared__ float red0[64], red1[64];
    __shared__ float cx, cy;

    if (tid == 0) {
        float bv = g_pval[m * 4]; int bi = g_pidx[m * 4];
        for (int s2 = 1; s2 < 4; ++s2) {
            float v = g_pval[m * 4 + s2]; int i2 = g_pidx[m * 4 + s2];
            if (v > bv || (v == bv && i2 < bi)) { bv = v; bi = i2; }
        }
        cx = (float)(bi % 512);          // width coord
        cy = (float)(bi / 512);          // height coord
    }
    __syncthreads();

    const float* imb = img + (size_t)b * IMH * IMW;
    for (int casc = 0; casc < 3; ++casc) {
        float lcx = cx, lcy = cy;
        int wi = (int)rintf(lcx * 0.25f);  wi = max(0, min(wi, 127));
        int hi = (int)rintf(lcy * 0.25f);  hi = max(0, min(hi, 127));
        float p0 = 0.f, p1 = 0.f;
        if (tid < 49) {
            int kh = tid / 7, kw = tid - kh * 7;
            int iy = hi * 4 - 3 + kh;
            int ix = wi * 4 - 3 + kw;
            float v = 0.f;
            if (iy >= 0 && iy < IMH && ix >= 0 && ix < IMW)
                v = imb[iy * IMW + ix] - 0.5f;
            p0 = v * c_params[OFF_CW + (casc * 2 + 0) * 49 + tid];
            p1 = v * c_params[OFF_CW + (casc * 2 + 1) * 49 + tid];
        }
        red0[tid] = p0; red1[tid] = p1;
        __syncthreads();
        for (int sft = 32; sft > 0; sft >>= 1) {
            if (tid < sft) { red0[tid] += red0[tid + sft]; red1[tid] += red1[tid + sft]; }
            __syncthreads();
        }
        if (tid == 0) {
            cx = lcx + red0[0] + c_params[OFF_CB + casc * 2 + 0];
            cy = lcy + red1[0] + c_params[OFF_CB + casc * 2 + 1];
        }
        __syncthreads();
    }
    if (tid == 0) { out[m * 2 + 0] = cx; out[m * 2 + 1] = cy; }
}

// ---------------------------------------------------------------------------
extern "C" void kernel_launch(void* const* d_in, const int* in_sizes, int n_in,
                              void* d_out, int out_size) {
    const float* img = (const float*)d_in[0];
    const float* bw  = (const float*)d_in[1];
    const float* bb  = (const float*)d_in[2];
    const float* fcw = (const float*)d_in[3];
    const float* fcb = (const float*)d_in[4];
    const float* hw  = (const float*)d_in[5];
    const float* hb  = (const float*)d_in[6];
    float* out = (float*)d_out;

    prep_kernel<<<1, 896>>>(bw, bb, fcw, fcb, hw, hb);

    void* src = nullptr;
    cudaGetSymbolAddress(&src, g_params_dev);
    cudaMemcpyToSymbolAsync(c_params, src, NPARAMS * sizeof(float), 0,
                            cudaMemcpyDeviceToDevice, 0);

    dim3 gconv(4, 8, BATCH);
    conv_kernel<<<gconv, 256>>>(img);

    dim3 gam(4, BATCH * NP);
    argmax_kernel<<<gam, 512>>>();

    cascade_kernel<<<BATCH * NP, 64>>>(img, out);
}

// round 3
// speedup vs baseline: 1.1480x; 1.1480x over previous
#include <cuda_runtime.h>
#include <math.h>

#define BATCH 8
#define IMH 512
#define IMW 512
#define NP 11
#define FH 128
#define FW 128

// packed derived parameters
// [0,539)    sw   : 11 score filters, 7x7 each          (sw[k*49+tap])
// [539,550)  sbias: 11 score biases
// [550,844)  cw   : 3 cascades x 2 dims x 49 taps       (cw[(i*2+j)*49+tap])
// [844,850)  cb   : 3 cascades x 2 dims
#define OFF_SW    0
#define OFF_SBIAS 539
#define OFF_CW    550
#define OFF_CB    844
#define NPARAMS   850

__device__    float g_params_dev[NPARAMS];
__constant__  float c_params[NPARAMS];

__device__ float g_scores[BATCH * NP * FH * FW];

// ---------------------------------------------------------------------------
// Kernel 1: fold weights. 1024 threads, w_eff staged in two 128-channel
// halves (static smem 24.5KB). Each warp owns outputs o = warp + 32*t and
// keeps lane-partials in registers across halves; one shuffle reduce at end.
//   w_eff[c,tap] = sum_i backbone_w[c,i,tap]
//   sw[k,tap]    = sum_c fc_w[k,c]*w_eff[c,tap];  sbias[k]=fc_b[k]+fc_w[k,:]·bb
//   cw[i,j,tap]  = sum_c head_w[i,c,j]*w_eff[c,tap]; cb[i,j]=hb[i,j]+hw[i,:,j]·bb
// ---------------------------------------------------------------------------
__global__ void prep_kernel(const float* __restrict__ bw,
                            const float* __restrict__ bb,
                            const float* __restrict__ fcw,
                            const float* __restrict__ fcb,
                            const float* __restrict__ hw,
                            const float* __restrict__ hb) {
    __shared__ float we[128 * 49];           // 24.5 KB
    const int tid = threadIdx.x;             // 1024
    const int w = tid >> 5, l = tid & 31;

    float acc[27];
    #pragma unroll
    for (int t = 0; t < 27; ++t) acc[t] = 0.f;

    for (int half = 0; half < 2; ++half) {
        __syncthreads();
        for (int idx = tid; idx < 128 * 49; idx += 1024) {
            int cl = idx / 49, p = idx - cl * 49;
            const float* base = bw + (half * 128 + cl) * 147 + p;
            we[idx] = base[0] + base[49] + base[98];
        }
        __syncthreads();

        for (int t = 0; t < 27; ++t) {
            int o = w + (t << 5);
            if (o >= 850) break;             // warp-uniform
            float a = 0.f;
            if (o < 833) {
                int grp = o / 49, p = o - grp * 49;
                if (grp < 11) {
                    #pragma unroll
                    for (int s = 0; s < 4; ++s) {
                        int cl = l + 32 * s;
                        a += fcw[grp * 256 + half * 128 + cl] * we[cl * 49 + p];
                    }
                } else {
                    int ij = grp - 11, i = ij >> 1, j = ij & 1;
                    #pragma unroll
                    for (int s = 0; s < 4; ++s) {
                        int cl = l + 32 * s;
                        a += hw[(i * 256 + half * 128 + cl) * 2 + j] * we[cl * 49 + p];
                    }
                }
            } else {
                int k = o - 833;
                if (k < 11) {
                    #pragma unroll
                    for (int s = 0; s < 4; ++s) {
                        int c = half * 128 + l + 32 * s;
                        a += fcw[k * 256 + c] * bb[c];
                    }
                } else {
                    int k2 = k - 11, i = k2 >> 1, j = k2 & 1;
                    #pragma unroll
                    for (int s = 0; s < 4; ++s) {
                        int c = half * 128 + l + 32 * s;
                        a += hw[(i * 256 + c) * 2 + j] * bb[c];
                    }
                }
            }
            acc[t] += a;
        }
    }

    for (int t = 0; t < 27; ++t) {
        int o = w + (t << 5);
        if (o >= 850) break;
        float a = acc[t];
        #pragma unroll
        for (int sft = 16; sft; sft >>= 1)
            a += __shfl_down_sync(0xffffffffu, a, sft);
        if (l == 0) {
            int slot; float base = 0.f;
            if (o < 539)       slot = OFF_SW + o;
            else if (o < 833)  slot = OFF_CW + (o - 539);
            else if (o < 844) { slot = OFF_SBIAS + (o - 833); base = fcb[o - 833]; }
            else              { slot = OFF_CB + (o - 844);    base = hb[o - 844]; }
            g_params_dev[slot] = base + a;
        }
    }
}

// ---------------------------------------------------------------------------
// Kernel 2: 11-channel 7x7 stride-4 pad-3 conv of normalized image -> scores.
// Block = batch x (16 x 32) output tile; input tile in smem; weights from
// __constant__ (uniform across block -> immediate-operand FFMAs).
// ---------------------------------------------------------------------------
__global__ void conv_kernel(const float* __restrict__ img) {
    __shared__ float tile[70 * 134];
    const int tx = blockIdx.x;
    const int ty = blockIdx.y;
    const int b  = blockIdx.z;
    const int tid = threadIdx.x;             // 256

    const float* imb = img + (size_t)b * IMH * IMW;
    const int ir0 = ty * 64 - 3;
    const int ic0 = tx * 128 - 3;

    for (int i = tid; i < 70 * 134; i += 256) {
        int r = i / 134, c = i - r * 134;
        int gr = ir0 + r, gc = ic0 + c;
        float v = 0.f;
        if (gr >= 0 && gr < IMH && gc >= 0 && gc < IMW)
            v = imb[gr * IMW + gc] - 0.5f;
        tile[i] = v;
    }
    __syncthreads();

    #pragma unroll
    for (int it = 0; it < 2; ++it) {
        int pos = tid + it * 256;
        int oyl = pos >> 5, oxl = pos & 31;
        float acc[NP];
        #pragma unroll
        for (int k = 0; k < NP; ++k) acc[k] = c_params[OFF_SBIAS + k];
        #pragma unroll
        for (int kh = 0; kh < 7; ++kh) {
            #pragma unroll
            for (int kw = 0; kw < 7; ++kw) {
                float v = tile[(oyl * 4 + kh) * 134 + oxl * 4 + kw];
                #pragma unroll
                for (int k = 0; k < NP; ++k)
                    acc[k] += v * c_params[OFF_SW + k * 49 + kh * 7 + kw];
            }
        }
        int oy = ty * 16 + oyl, ox = tx * 32 + oxl;
        #pragma unroll
        for (int k = 0; k < NP; ++k)
            g_scores[((b * NP + k) * FH + oy) * FW + ox] = acc[k];
    }
}

// ---------------------------------------------------------------------------
// Kernel 3: fused argmax + cascades. One block per (b,point) map, 512 thr.
// Bilinear field is linear in wy within each cell-row group (same y0) ->
// group max over output rows is attained at an endpoint row: evaluate 2
// candidates per group (exact reference arithmetic). Score map processed in
// two 64-group row halves so static smem stays under 48KB (no attr opt-in).
// Then block argmax (first-occurrence tie-break), then 3 cascades in warp 0.
// ---------------------------------------------------------------------------
__global__ void argmax_cascade_kernel(const float* __restrict__ img,
                                      float* __restrict__ out) {
    __shared__ float s[65 * 128];             // 33280 B
    __shared__ float wlo[128], whi[128];
    __shared__ int   flo[128], fhi[128];
    __shared__ float rv[512];
    __shared__ int   ri[512];

    const int m   = blockIdx.x;               // b*11 + k
    const int tid = threadIdx.x;              // 512
    const float STEP = 127.0f / 511.0f;
    const float* smap = g_scores + (size_t)m * FH * FW;

    if (tid < 128) flo[tid] = -1;
    __syncthreads();
    // per-group row tables (group g = cell row y0=g): first/last output row
    {
        int oy = tid;
        float ys = (float)oy * STEP;
        int y0 = (int)ys;
        float wy = ys - (float)y0;
        int y0m = (oy > 0)   ? (int)((float)(oy - 1) * STEP) : -1;
        int y0p = (oy < 511) ? (int)((float)(oy + 1) * STEP) : 128;
        if (y0m != y0) { flo[y0] = oy; wlo[y0] = wy; }
        if (y0p != y0) { fhi[y0] = oy; whi[y0] = wy; }
    }

    const int ox = tid;
    float xs = (float)ox * STEP;
    int x0 = (int)xs;
    int x1 = min(x0 + 1, 127);
    float wx = xs - (float)x0, omwx = 1.f - wx;

    float best = -3.0e38f;
    int bidx = 0x7fffffff;
    float a = 0.f, b = 0.f;

    for (int half = 0; half < 2; ++half) {
        __syncthreads();
        // load rows [half*64, half*64+nrows)
        int rbase = half * 64;
        int nrows = half ? 64 : 65;
        {
            const float4* src = (const float4*)(smap + rbase * 128);
            float4* dst = (float4*)s;
            int n4 = nrows * 32;              // float4 count
            for (int i = tid; i < n4; i += 512) dst[i] = src[i];
        }
        __syncthreads();

        if (half == 0) { a = s[x0]; b = s[x1]; }

        int gend = rbase + 64;
        #pragma unroll 4
        for (int g = rbase; g < gend; ++g) {
            int y1l = min(g + 1, 127) - rbase;
            float c = s[y1l * 128 + x0];
            float d = s[y1l * 128 + x1];
            int olo = flo[g];
            if (olo >= 0) {
                float wl = wlo[g], wh = whi[g];
                float ol = 1.f - wl, oh = 1.f - wh;
                float vl = (a * ol + c * wl) * omwx + (b * ol + d * wl) * wx;
                float vh = (a * oh + c * wh) * omwx + (b * oh + d * wh) * wx;
                float v; int oy;
                if (vh > vl) { v = vh; oy = fhi[g]; }
                else         { v = vl; oy = olo;    }
                if (v > best) { best = v; bidx = (oy << 9) + ox; }
            }
            a = c; b = d;
        }
    }

    __syncthreads();
    rv[tid] = best; ri[tid] = bidx;
    __syncthreads();
    for (int sft = 256; sft; sft >>= 1) {
        if (tid < sft) {
            float v2 = rv[tid + sft]; int i2 = ri[tid + sft];
            if (v2 > rv[tid] || (v2 == rv[tid] && i2 < ri[tid])) {
                rv[tid] = v2; ri[tid] = i2;
            }
        }
        __syncthreads();
    }

    // cascades in warp 0 (shuffle reductions only)
    if (tid < 32) {
        int bi = ri[0];
        float cx = (float)(bi & 511);
        float cy = (float)(bi >> 9);
        const float* imb = img + (size_t)(m / NP) * IMH * IMW;

        for (int casc = 0; casc < 3; ++casc) {
            int wi = (int)rintf(cx * 0.25f); wi = max(0, min(wi, 127));
            int hi = (int)rintf(cy * 0.25f); hi = max(0, min(hi, 127));
            float p0 = 0.f, p1 = 0.f;
            for (int t = tid; t < 49; t += 32) {
                int kh = t / 7, kw = t - kh * 7;
                int iy = hi * 4 - 3 + kh;
                int ix = wi * 4 - 3 + kw;
                float v = 0.f;
                if (iy >= 0 && iy < IMH && ix >= 0 && ix < IMW)
                    v = imb[iy * IMW + ix] - 0.5f;
                p0 += v * c_params[OFF_CW + (casc * 2 + 0) * 49 + t];
                p1 += v * c_params[OFF_CW + (casc * 2 + 1) * 49 + t];
            }
            #pragma unroll
            for (int sft = 16; sft; sft >>= 1) {
                p0 += __shfl_down_sync(0xffffffffu, p0, sft);
                p1 += __shfl_down_sync(0xffffffffu, p1, sft);
            }
            p0 = __shfl_sync(0xffffffffu, p0, 0);
            p1 = __shfl_sync(0xffffffffu, p1, 0);
            cx = cx + p0 + c_params[OFF_CB + casc * 2 + 0];
            cy = cy + p1 + c_params[OFF_CB + casc * 2 + 1];
        }
        if (tid == 0) { out[m * 2 + 0] = cx; out[m * 2 + 1] = cy; }
    }
}

// ---------------------------------------------------------------------------
extern "C" void kernel_launch(void* const* d_in, const int* in_sizes, int n_in,
                              void* d_out, int out_size) {
    const float* img = (const float*)d_in[0];
    const float* bw  = (const float*)d_in[1];
    const float* bb  = (const float*)d_in[2];
    const float* fcw = (const float*)d_in[3];
    const float* fcb = (const float*)d_in[4];
    const float* hw  = (const float*)d_in[5];
    const float* hb  = (const float*)d_in[6];
    float* out = (float*)d_out;

    prep_kernel<<<1, 1024>>>(bw, bb, fcw, fcb, hw, hb);

    void* src = nullptr;
    cudaGetSymbolAddress(&src, g_params_dev);
    cudaMemcpyToSymbolAsync(c_params, src, NPARAMS * sizeof(float), 0,
                            cudaMemcpyDeviceToDevice, 0);

    dim3 gconv(4, 8, BATCH);
    conv_kernel<<<gconv, 256>>>(img);

    argmax_cascade_kernel<<<BATCH * NP, 512>>>(img, out);
}

// round 4
// speedup vs baseline: 1.9592x; 1.7066x over previous
#include <cuda_runtime.h>
#include <math.h>

#define BATCH 8
#define IMH 512
#define IMW 512
#define NP 11
#define FH 128
#define FW 128

// packed derived parameters
// [0,539)    sw   : 11 score filters, 7x7 each          (sw[k*49+tap])
// [539,550)  sbias: 11 score biases
// [550,844)  cw   : 3 cascades x 2 dims x 49 taps       (cw[(i*2+j)*49+tap])
// [844,850)  cb   : 3 cascades x 2 dims
#define OFF_SW    0
#define OFF_SBIAS 539
#define OFF_CW    550
#define OFF_CB    844
#define NPARAMS   850

__device__    float g_params_dev[NPARAMS];
__constant__  float c_params[NPARAMS];

__device__ float g_scores[BATCH * NP * FH * FW];

// ---------------------------------------------------------------------------
// Kernel 1: fold weights — one warp per output, grid-parallel, scalar acc.
// Output index space o in [0,850):
//   o < 539          : sw[o]      = sum_c fc_w[o/49,c] * w_eff[c, o%49]
//   539 <= o < 833   : cw[o-539]  = sum_c head_w[i,c,j] * w_eff[c,p]
//   833 <= o < 844   : sbias[k]   = fc_b[k] + sum_c fc_w[k,c]*bb[c]
//   844 <= o < 850   : cb[ij]     = hb[ij]  + sum_c head_w[i,c,j]*bb[c]
// with w_eff[c,p] = bw[c,0,p]+bw[c,1,p]+bw[c,2,p] (3 identical input chans).
// ---------------------------------------------------------------------------
__global__ void prep_kernel(const float* __restrict__ bw,
                            const float* __restrict__ bb,
                            const float* __restrict__ fcw,
                            const float* __restrict__ fcb,
                            const float* __restrict__ hw,
                            const float* __restrict__ hb) {
    const int o = (blockIdx.x * blockDim.x + threadIdx.x) >> 5;
    const int l = threadIdx.x & 31;
    if (o >= 850) return;

    float acc = 0.f;
    if (o < 833) {
        const int grp = o / 49, p = o - grp * 49;     // warp-uniform
        if (grp < 11) {
            #pragma unroll
            for (int s = 0; s < 8; ++s) {
                int c = l + 32 * s;
                const float* base = bw + c * 147 + p;
                float we = base[0] + base[49] + base[98];
                acc += fcw[grp * 256 + c] * we;
            }
        } else {
            const int ij = grp - 11, i = ij >> 1, j = ij & 1;
            #pragma unroll
            for (int s = 0; s < 8; ++s) {
                int c = l + 32 * s;
                const float* base = bw + c * 147 + p;
                float we = base[0] + base[49] + base[98];
                acc += hw[(i * 256 + c) * 2 + j] * we;
            }
        }
    } else if (o < 844) {
        const int k = o - 833;
        #pragma unroll
        for (int s = 0; s < 8; ++s) {
            int c = l + 32 * s;
            acc += fcw[k * 256 + c] * bb[c];
        }
    } else {
        const int ij = o - 844, i = ij >> 1, j = ij & 1;
        #pragma unroll
        for (int s = 0; s < 8; ++s) {
            int c = l + 32 * s;
            acc += hw[(i * 256 + c) * 2 + j] * bb[c];
        }
    }

    #pragma unroll
    for (int sft = 16; sft; sft >>= 1)
        acc += __shfl_down_sync(0xffffffffu, acc, sft);

    if (l == 0) {
        int slot; float base = 0.f;
        if (o < 539)       slot = OFF_SW + o;
        else if (o < 833)  slot = OFF_CW + (o - 539);
        else if (o < 844) { slot = OFF_SBIAS + (o - 833); base = fcb[o - 833]; }
        else              { slot = OFF_CB + (o - 844);    base = hb[o - 844]; }
        g_params_dev[slot] = base + acc;
    }
}

// ---------------------------------------------------------------------------
// Kernel 2: 11-channel 7x7 stride-4 pad-3 conv of normalized image -> scores.
// Block = batch x (16 x 32) output tile; input tile in smem; weights from
// __constant__ (uniform across block -> immediate-operand FFMAs).
// ---------------------------------------------------------------------------
__global__ void conv_kernel(const float* __restrict__ img) {
    __shared__ float tile[70 * 134];
    const int tx = blockIdx.x;
    const int ty = blockIdx.y;
    const int b  = blockIdx.z;
    const int tid = threadIdx.x;             // 256

    const float* imb = img + (size_t)b * IMH * IMW;
    const int ir0 = ty * 64 - 3;
    const int ic0 = tx * 128 - 3;

    for (int i = tid; i < 70 * 134; i += 256) {
        int r = i / 134, c = i - r * 134;
        int gr = ir0 + r, gc = ic0 + c;
        float v = 0.f;
        if (gr >= 0 && gr < IMH && gc >= 0 && gc < IMW)
            v = imb[gr * IMW + gc] - 0.5f;
        tile[i] = v;
    }
    __syncthreads();

    #pragma unroll
    for (int it = 0; it < 2; ++it) {
        int pos = tid + it * 256;
        int oyl = pos >> 5, oxl = pos & 31;
        float acc[NP];
        #pragma unroll
        for (int k = 0; k < NP; ++k) acc[k] = c_params[OFF_SBIAS + k];
        #pragma unroll
        for (int kh = 0; kh < 7; ++kh) {
            #pragma unroll
            for (int kw = 0; kw < 7; ++kw) {
                float v = tile[(oyl * 4 + kh) * 134 + oxl * 4 + kw];
                #pragma unroll
                for (int k = 0; k < NP; ++k)
                    acc[k] += v * c_params[OFF_SW + k * 49 + kh * 7 + kw];
            }
        }
        int oy = ty * 16 + oyl, ox = tx * 32 + oxl;
        #pragma unroll
        for (int k = 0; k < NP; ++k)
            g_scores[((b * NP + k) * FH + oy) * FW + ox] = acc[k];
    }
}

// ---------------------------------------------------------------------------
// Kernel 3: fused argmax + cascades. One block per (b,point) map, 512 thr.
// Bilinear field is linear in wy within each cell-row group (same y0) ->
// group max over output rows is attained at an endpoint row: evaluate 2
// candidates per group (exact reference arithmetic). Score map processed in
// two 64-group row halves so static smem stays under 48KB (no attr opt-in).
// Then block argmax (first-occurrence tie-break), then 3 cascades in warp 0.
// ---------------------------------------------------------------------------
__global__ void argmax_cascade_kernel(const float* __restrict__ img,
                                      float* __restrict__ out) {
    __shared__ float s[65 * 128];             // 33280 B
    __shared__ float wlo[128], whi[128];
    __shared__ int   flo[128], fhi[128];
    __shared__ float rv[512];
    __shared__ int   ri[512];

    const int m   = blockIdx.x;               // b*11 + k
    const int tid = threadIdx.x;              // 512
    const float STEP = 127.0f / 511.0f;
    const float* smap = g_scores + (size_t)m * FH * FW;

    if (tid < 128) flo[tid] = -1;
    __syncthreads();
    // per-group row tables (group g = cell row y0=g): first/last output row
    {
        int oy = tid;
        float ys = (float)oy * STEP;
        int y0 = (int)ys;
        float wy = ys - (float)y0;
        int y0m = (oy > 0)   ? (int)((float)(oy - 1) * STEP) : -1;
        int y0p = (oy < 511) ? (int)((float)(oy + 1) * STEP) : 128;
        if (y0m != y0) { flo[y0] = oy; wlo[y0] = wy; }
        if (y0p != y0) { fhi[y0] = oy; whi[y0] = wy; }
    }

    const int ox = tid;
    float xs = (float)ox * STEP;
    int x0 = (int)xs;
    int x1 = min(x0 + 1, 127);
    float wx = xs - (float)x0, omwx = 1.f - wx;

    float best = -3.0e38f;
    int bidx = 0x7fffffff;
    float a = 0.f, b = 0.f;

    for (int half = 0; half < 2; ++half) {
        __syncthreads();
        int rbase = half * 64;
        int nrows = half ? 64 : 65;
        {
            const float4* src = (const float4*)(smap + rbase * 128);
            float4* dst = (float4*)s;
            int n4 = nrows * 32;
            for (int i = tid; i < n4; i += 512) dst[i] = src[i];
        }
        __syncthreads();

        if (half == 0) { a = s[x0]; b = s[x1]; }

        int gend = rbase + 64;
        #pragma unroll 4
        for (int g = rbase; g < gend; ++g) {
            int y1l = min(g + 1, 127) - rbase;
            float c = s[y1l * 128 + x0];
            float d = s[y1l * 128 + x1];
            int olo = flo[g];
            if (olo >= 0) {
                float wl = wlo[g], wh = whi[g];
                float ol = 1.f - wl, oh = 1.f - wh;
                float vl = (a * ol + c * wl) * omwx + (b * ol + d * wl) * wx;
                float vh = (a * oh + c * wh) * omwx + (b * oh + d * wh) * wx;
                float v; int oy;
                if (vh > vl) { v = vh; oy = fhi[g]; }
                else         { v = vl; oy = olo;    }
                if (v > best) { best = v; bidx = (oy << 9) + ox; }
            }
            a = c; b = d;
        }
    }

    __syncthreads();
    rv[tid] = best; ri[tid] = bidx;
    __syncthreads();
    for (int sft = 256; sft; sft >>= 1) {
        if (tid < sft) {
            float v2 = rv[tid + sft]; int i2 = ri[tid + sft];
            if (v2 > rv[tid] || (v2 == rv[tid] && i2 < ri[tid])) {
                rv[tid] = v2; ri[tid] = i2;
            }
        }
        __syncthreads();
    }

    // cascades in warp 0 (shuffle reductions only)
    if (tid < 32) {
        int bi = ri[0];
        float cx = (float)(bi & 511);
        float cy = (float)(bi >> 9);
        const float* imb = img + (size_t)(m / NP) * IMH * IMW;

        for (int casc = 0; casc < 3; ++casc) {
            int wi = (int)rintf(cx * 0.25f); wi = max(0, min(wi, 127));
            int hi = (int)rintf(cy * 0.25f); hi = max(0, min(hi, 127));
            float p0 = 0.f, p1 = 0.f;
            for (int t = tid; t < 49; t += 32) {
                int kh = t / 7, kw = t - kh * 7;
                int iy = hi * 4 - 3 + kh;
                int ix = wi * 4 - 3 + kw;
                float v = 0.f;
                if (iy >= 0 && iy < IMH && ix >= 0 && ix < IMW)
                    v = imb[iy * IMW + ix] - 0.5f;
                p0 += v * c_params[OFF_CW + (casc * 2 + 0) * 49 + t];
                p1 += v * c_params[OFF_CW + (casc * 2 + 1) * 49 + t];
            }
            #pragma unroll
            for (int sft = 16; sft; sft >>= 1) {
                p0 += __shfl_down_sync(0xffffffffu, p0, sft);
                p1 += __shfl_down_sync(0xffffffffu, p1, sft);
            }
            p0 = __shfl_sync(0xffffffffu, p0, 0);
            p1 = __shfl_sync(0xffffffffu, p1, 0);
            cx = cx + p0 + c_params[OFF_CB + casc * 2 + 0];
            cy = cy + p1 + c_params[OFF_CB + casc * 2 + 1];
        }
        if (tid == 0) { out[m * 2 + 0] = cx; out[m * 2 + 1] = cy; }
    }
}

// ---------------------------------------------------------------------------
extern "C" void kernel_launch(void* const* d_in, const int* in_sizes, int n_in,
                              void* d_out, int out_size) {
    const float* img = (const float*)d_in[0];
    const float* bw  = (const float*)d_in[1];
    const float* bb  = (const float*)d_in[2];
    const float* fcw = (const float*)d_in[3];
    const float* fcb = (const float*)d_in[4];
    const float* hw  = (const float*)d_in[5];
    const float* hb  = (const float*)d_in[6];
    float* out = (float*)d_out;

    // 850 outputs, one warp each: 213 blocks x 128 threads = 852 warps
    prep_kernel<<<213, 128>>>(bw, bb, fcw, fcb, hw, hb);

    void* src = nullptr;
    cudaGetSymbolAddress(&src, g_params_dev);
    cudaMemcpyToSymbolAsync(c_params, src, NPARAMS * sizeof(float), 0,
                            cudaMemcpyDeviceToDevice, 0);

    dim3 gconv(4, 8, BATCH);
    conv_kernel<<<gconv, 256>>>(img);

    argmax_cascade_kernel<<<BATCH * NP, 512>>>(img, out);
}